// round 5
// baseline (speedup 1.0000x reference)
#include <cuda_runtime.h>
#include <math.h>

#define N_ENT   40000
#define N_REL   500
#define E_DIRN  200000
#define E_2HOP  50000
#define E_TOT   250000
#define D_IN    128
#define D_EMB   256
#define NHEADS  4
#define NHID    64

// ---------------- scratch (device globals; no allocation allowed) ----------
__device__ __align__(16) float g_AB[(size_t)N_ENT * 512];      // [A(256) | B(256)] per entity
__device__ __align__(16) float g_Crel[N_REL * 256];            // edge-part projection per relation (layer1)
__device__ float g_aA[N_ENT * 4];
__device__ float g_aB[N_ENT * 4];
__device__ float g_aC[N_REL * 4];
__device__ float g_ew[E_TOT * 4];                              // exp(logit) layer1
__device__ float g_s1[N_ENT * 4];                              // softmax denominators layer1
__device__ __align__(16) float g_agg1[(size_t)N_ENT * 256];    // agg layer1 -> x (in place)
__device__ __align__(16) float g_X12[(size_t)N_ENT * 512];     // [X1 | X2] layer2
__device__ __align__(16) float g_R3[N_REL * 256];              // r @ W3
__device__ float g_bx1[N_ENT];
__device__ float g_bx2[N_ENT];
__device__ float g_bR[N_REL];
__device__ float g_ew2[E_TOT];
__device__ float g_s2[N_ENT];
__device__ __align__(16) float g_agg2[(size_t)N_ENT * 256];
__device__ __align__(16) float g_ENT[(size_t)N_ENT * 256];     // init_embed @ W_entities
__device__ __align__(16) float g_r[N_REL * 256];               // init_rel @ gat_W
__device__ __align__(16) float g_W1ab[128 * 512];              // packed layer1 [row|col] weights
__device__ __align__(16) float g_W1e[128 * 256];               // packed layer1 edge weights
__device__ __align__(16) float g_W2ab[256 * 512];              // packed layer2 [row|col] weights
__device__ float g_csum[256];
__device__ float g_csq[256];

// ---------------- zero scratch (must be re-zeroed every replay) ------------
__global__ void zero_kernel() {
    size_t i = (size_t)blockIdx.x * blockDim.x + threadIdx.x;
    size_t stride = (size_t)gridDim.x * blockDim.x;
    for (size_t k = i; k < (size_t)N_ENT * 256; k += stride) { g_agg1[k] = 0.f; g_agg2[k] = 0.f; }
    for (size_t k = i; k < (size_t)N_ENT * 4; k += stride) g_s1[k] = 0.f;
    for (size_t k = i; k < (size_t)N_ENT; k += stride) g_s2[k] = 0.f;
    if (i < 256) { g_csum[i] = 0.f; g_csq[i] = 0.f; }
}

// ---------------- weight packing -------------------------------------------
// W_heads: (4, 384, 64) row-major. g_W1ab[k*512+j]:
//   j<256:   head h=j/64, col c=j%64, source row k       (multiplies init_embed[row])
//   j>=256:  source row 128+k                            (multiplies init_embed[col])
// g_W1e[k*256+j]: source row 256+k                       (multiplies edge_embed)
__global__ void pack_w1(const float* __restrict__ W_heads) {
    int gid = blockIdx.x * blockDim.x + threadIdx.x;
    int stride = gridDim.x * blockDim.x;
    for (int idx = gid; idx < 128 * 512; idx += stride) {
        int k = idx >> 9, j = idx & 511;
        int part = (j < 256) ? 0 : 1;
        int jj = j & 255;
        int h = jj >> 6, c = jj & 63;
        g_W1ab[idx] = W_heads[h * (384 * 64) + (part * 128 + k) * 64 + c];
    }
    for (int idx = gid; idx < 128 * 256; idx += stride) {
        int k = idx >> 8, j = idx & 255;
        int h = j >> 6, c = j & 63;
        g_W1e[idx] = W_heads[h * (384 * 64) + (256 + k) * 64 + c];
    }
}

// out_W: (768, 256). g_W2ab[k*512+j] = out_W[(j<256 ? k : 256+k)*256 + (j%256)]
__global__ void pack_w2(const float* __restrict__ out_W) {
    int gid = blockIdx.x * blockDim.x + threadIdx.x;
    int stride = gridDim.x * blockDim.x;
    for (int idx = gid; idx < 256 * 512; idx += stride) {
        int k = idx >> 9, j = idx & 511;
        int src_row = (j < 256) ? k : (256 + k);
        g_W2ab[idx] = out_W[src_row * 256 + (j & 255)];
    }
}

// ---------------- SGEMM: C[MxN] = A[MxK] @ B[KxN], row-major ---------------
// N % 128 == 0, K % 8 == 0 (true for all call sites); arbitrary M.
__global__ __launch_bounds__(256, 2) void sgemm_kernel(
    int M, int N, int K,
    const float* __restrict__ A, const float* __restrict__ B, float* __restrict__ C)
{
    const int BM = 128, BN = 128, BK = 8, TM = 8, TN = 8;
    __shared__ float As[BK][BM];
    __shared__ float Bs[BK][BN];
    const int tid = threadIdx.x;
    const int crow = (tid / (BN / TN)) * TM;   // 0,8,...,120
    const int ccol = (tid % (BN / TN)) * TN;
    const int mBase = blockIdx.y * BM;
    const int nBase = blockIdx.x * BN;
    const int aRow = tid >> 1;                 // 0..127
    const int aCol = (tid & 1) * 4;            // 0 or 4
    const int bRow = tid >> 5;                 // 0..7
    const int bCol = (tid & 31) * 4;

    const float* Ap = A + (size_t)mBase * K;
    const float* Bp = B + nBase;
    float* Cp = C + (size_t)mBase * N + nBase;

    float acc[TM][TN];
#pragma unroll
    for (int i = 0; i < TM; i++)
#pragma unroll
        for (int j = 0; j < TN; j++) acc[i][j] = 0.f;

    for (int k0 = 0; k0 < K; k0 += BK) {
        float4 av;
        if (mBase + aRow < M)
            av = *(const float4*)&Ap[(size_t)aRow * K + k0 + aCol];
        else
            av = make_float4(0.f, 0.f, 0.f, 0.f);
        As[aCol + 0][aRow] = av.x;
        As[aCol + 1][aRow] = av.y;
        As[aCol + 2][aRow] = av.z;
        As[aCol + 3][aRow] = av.w;
        float4 bv = *(const float4*)&Bp[(size_t)(k0 + bRow) * N + bCol];
        *(float4*)&Bs[bRow][bCol] = bv;
        __syncthreads();
#pragma unroll
        for (int k = 0; k < BK; k++) {
            float ra[TM], rb[TN];
#pragma unroll
            for (int i = 0; i < TM; i++) ra[i] = As[k][crow + i];
#pragma unroll
            for (int j = 0; j < TN; j++) rb[j] = Bs[k][ccol + j];
#pragma unroll
            for (int i = 0; i < TM; i++)
#pragma unroll
                for (int j = 0; j < TN; j++) acc[i][j] += ra[i] * rb[j];
        }
        __syncthreads();
    }
#pragma unroll
    for (int i = 0; i < TM; i++) {
        if (mBase + crow + i < M) {
            *(float4*)&Cp[(size_t)(crow + i) * N + ccol]     = make_float4(acc[i][0], acc[i][1], acc[i][2], acc[i][3]);
            *(float4*)&Cp[(size_t)(crow + i) * N + ccol + 4] = make_float4(acc[i][4], acc[i][5], acc[i][6], acc[i][7]);
        }
    }
}

// ---------------- scalar projections ---------------------------------------
__global__ void dots_ab(const float* __restrict__ a_heads) {
    int w = (blockIdx.x * blockDim.x + threadIdx.x) >> 5;
    int lane = threadIdx.x & 31;
    if (w >= N_ENT) return;
    const float* p = g_AB + (size_t)w * 512;
#pragma unroll
    for (int h = 0; h < 4; h++) {
        float a0 = a_heads[h * 64 + lane];
        float a1 = a_heads[h * 64 + 32 + lane];
        float sA = p[h * 64 + lane] * a0 + p[h * 64 + 32 + lane] * a1;
        float sB = p[256 + h * 64 + lane] * a0 + p[256 + h * 64 + 32 + lane] * a1;
#pragma unroll
        for (int o = 16; o; o >>= 1) {
            sA += __shfl_xor_sync(0xffffffffu, sA, o);
            sB += __shfl_xor_sync(0xffffffffu, sB, o);
        }
        if (lane == 0) { g_aA[w * 4 + h] = sA; g_aB[w * 4 + h] = sB; }
    }
}

__global__ void dots_c(const float* __restrict__ a_heads) {
    int t = blockIdx.x * blockDim.x + threadIdx.x;
    if (t >= N_REL * 4) return;
    int r = t >> 2, h = t & 3;
    float s = 0.f;
    for (int j = 0; j < 64; j++) s += g_Crel[r * 256 + h * 64 + j] * a_heads[h * 64 + j];
    g_aC[t] = s;
}

__global__ void dots_x(const float* __restrict__ out_a) {
    int w = (blockIdx.x * blockDim.x + threadIdx.x) >> 5;
    int lane = threadIdx.x & 31;
    if (w >= 2 * N_ENT) return;
    int i = w >> 1, sel = w & 1;
    const float* p = g_X12 + (size_t)i * 512 + sel * 256;
    float s = 0.f;
    for (int d = lane; d < 256; d += 32) s += p[d] * out_a[d];
#pragma unroll
    for (int o = 16; o; o >>= 1) s += __shfl_xor_sync(0xffffffffu, s, o);
    if (lane == 0) { if (sel) g_bx2[i] = s; else g_bx1[i] = s; }
}

__global__ void dots_r(const float* __restrict__ out_a) {
    int w = (blockIdx.x * blockDim.x + threadIdx.x) >> 5;
    int lane = threadIdx.x & 31;
    if (w >= N_REL) return;
    float s = 0.f;
    for (int d = lane; d < 256; d += 32) s += g_R3[w * 256 + d] * out_a[d];
#pragma unroll
    for (int o = 16; o; o >>= 1) s += __shfl_xor_sync(0xffffffffu, s, o);
    if (lane == 0) g_bR[w] = s;
}

// ---------------- layer 1 edge passes --------------------------------------
__global__ void edge_logits1(const int* __restrict__ ei, const int* __restrict__ et,
                             const int* __restrict__ i2) {
    int e = blockIdx.x * blockDim.x + threadIdx.x;
    if (e >= E_TOT) return;
    int row, col;
    float c[4];
    if (e < E_DIRN) {
        row = ei[E_DIRN + e];
        col = ei[e];
        int t = et[e];
#pragma unroll
        for (int h = 0; h < 4; h++) c[h] = g_aC[t * 4 + h];
    } else {
        int q = (e - E_DIRN) * 4;
        row = i2[q + 3]; col = i2[q + 0];
        int t0 = i2[q + 1], t1 = i2[q + 2];
#pragma unroll
        for (int h = 0; h < 4; h++) c[h] = g_aC[t0 * 4 + h] + g_aC[t1 * 4 + h];
    }
#pragma unroll
    for (int h = 0; h < 4; h++) {
        float l = g_aA[row * 4 + h] + g_aB[col * 4 + h] + c[h];
        l = (l > 0.f) ? l : 0.2f * l;           // leaky_relu
        float w = expf(l);                       // logits are O(1): no max-shift needed
        g_ew[e * 4 + h] = w;
        atomicAdd(&g_s1[row * 4 + h], w);
    }
}

__global__ void edge_scatter1(const int* __restrict__ ei, const int* __restrict__ et,
                              const int* __restrict__ i2) {
    int e = (blockIdx.x * blockDim.x + threadIdx.x) >> 5;
    int lane = threadIdx.x & 31;
    if (e >= E_TOT) return;
    int row, col;
    const float* C0;
    const float* C1 = nullptr;
    if (e < E_DIRN) {
        row = ei[E_DIRN + e];
        col = ei[e];
        C0 = g_Crel + et[e] * 256;
    } else {
        int q = (e - E_DIRN) * 4;
        row = i2[q + 3]; col = i2[q + 0];
        C0 = g_Crel + i2[q + 1] * 256;
        C1 = g_Crel + i2[q + 2] * 256;
    }
    int d = lane * 8;
    int h = lane >> 3;                           // 8 dims per lane stay within one head
    float alpha = g_ew[e * 4 + h] / (g_s1[row * 4 + h] + 1e-16f);
    const float* Bp = g_AB + (size_t)col * 512 + 256;
    float* Ap = g_agg1 + (size_t)row * 256;
    float4 v0 = *(const float4*)(Bp + d);
    float4 v1 = *(const float4*)(Bp + d + 4);
    float4 c0 = *(const float4*)(C0 + d);
    float4 c1 = *(const float4*)(C0 + d + 4);
    v0.x += c0.x; v0.y += c0.y; v0.z += c0.z; v0.w += c0.w;
    v1.x += c1.x; v1.y += c1.y; v1.z += c1.z; v1.w += c1.w;
    if (C1) {
        float4 e0 = *(const float4*)(C1 + d);
        float4 e1 = *(const float4*)(C1 + d + 4);
        v0.x += e0.x; v0.y += e0.y; v0.z += e0.z; v0.w += e0.w;
        v1.x += e1.x; v1.y += e1.y; v1.z += e1.z; v1.w += e1.w;
    }
    atomicAdd(Ap + d + 0, alpha * v0.x);
    atomicAdd(Ap + d + 1, alpha * v0.y);
    atomicAdd(Ap + d + 2, alpha * v0.z);
    atomicAdd(Ap + d + 3, alpha * v0.w);
    atomicAdd(Ap + d + 4, alpha * v1.x);
    atomicAdd(Ap + d + 5, alpha * v1.y);
    atomicAdd(Ap + d + 6, alpha * v1.z);
    atomicAdd(Ap + d + 7, alpha * v1.w);
}

// x = elu(agg + A[v] * sum_alpha), where sum_alpha = s/(s+1e-16)
__global__ void finalize1() {
    size_t gid = (size_t)blockIdx.x * blockDim.x + threadIdx.x;
    if (gid >= (size_t)N_ENT * 256) return;
    int v = (int)(gid >> 8);
    int d = (int)(gid & 255);
    int h = d >> 6;
    float s = g_s1[v * 4 + h];
    float S = s / (s + 1e-16f);
    float val = g_agg1[gid] + g_AB[(size_t)v * 512 + d] * S;
    g_agg1[gid] = (val > 0.f) ? val : expm1f(val);
}

// ---------------- layer 2 edge passes --------------------------------------
__global__ void edge_logits2(const int* __restrict__ ei, const int* __restrict__ et,
                             const int* __restrict__ i2) {
    int e = blockIdx.x * blockDim.x + threadIdx.x;
    if (e >= E_TOT) return;
    int row, col;
    float c;
    if (e < E_DIRN) {
        row = ei[E_DIRN + e]; col = ei[e];
        c = g_bR[et[e]];
    } else {
        int q = (e - E_DIRN) * 4;
        row = i2[q + 3]; col = i2[q + 0];
        c = g_bR[i2[q + 1]] + g_bR[i2[q + 2]];
    }
    float l = g_bx1[row] + g_bx2[col] + c;
    l = (l > 0.f) ? l : 0.2f * l;
    float w = expf(l);
    g_ew2[e] = w;
    atomicAdd(&g_s2[row], w);
}

__global__ void edge_scatter2(const int* __restrict__ ei, const int* __restrict__ et,
                              const int* __restrict__ i2) {
    int e = (blockIdx.x * blockDim.x + threadIdx.x) >> 5;
    int lane = threadIdx.x & 31;
    if (e >= E_TOT) return;
    int row, col;
    const float* C0;
    const float* C1 = nullptr;
    if (e < E_DIRN) {
        row = ei[E_DIRN + e]; col = ei[e];
        C0 = g_R3 + et[e] * 256;
    } else {
        int q = (e - E_DIRN) * 4;
        row = i2[q + 3]; col = i2[q + 0];
        C0 = g_R3 + i2[q + 1] * 256;
        C1 = g_R3 + i2[q + 2] * 256;
    }
    float alpha = g_ew2[e] / (g_s2[row] + 1e-16f);
    int d = lane * 8;
    const float* Xp = g_X12 + (size_t)col * 512 + 256;   // X2 half
    float* Ap = g_agg2 + (size_t)row * 256;
    float4 v0 = *(const float4*)(Xp + d);
    float4 v1 = *(const float4*)(Xp + d + 4);
    float4 c0 = *(const float4*)(C0 + d);
    float4 c1 = *(const float4*)(C0 + d + 4);
    v0.x += c0.x; v0.y += c0.y; v0.z += c0.z; v0.w += c0.w;
    v1.x += c1.x; v1.y += c1.y; v1.z += c1.z; v1.w += c1.w;
    if (C1) {
        float4 e0 = *(const float4*)(C1 + d);
        float4 e1 = *(const float4*)(C1 + d + 4);
        v0.x += e0.x; v0.y += e0.y; v0.z += e0.z; v0.w += e0.w;
        v1.x += e1.x; v1.y += e1.y; v1.z += e1.z; v1.w += e1.w;
    }
    atomicAdd(Ap + d + 0, alpha * v0.x);
    atomicAdd(Ap + d + 1, alpha * v0.y);
    atomicAdd(Ap + d + 2, alpha * v0.z);
    atomicAdd(Ap + d + 3, alpha * v0.w);
    atomicAdd(Ap + d + 4, alpha * v1.x);
    atomicAdd(Ap + d + 5, alpha * v1.y);
    atomicAdd(Ap + d + 6, alpha * v1.z);
    atomicAdd(Ap + d + 7, alpha * v1.w);
}

// out = elu(agg2 + X1[v]*S) + ENT[v]; also accumulate per-column sum / sumsq
#define ROWS_PER_BLK 128
__global__ void finalize2_bn(float* __restrict__ out) {
    int ct = threadIdx.x;                        // column 0..255
    int r0 = blockIdx.x * ROWS_PER_BLK;
    int r1 = min(r0 + ROWS_PER_BLK, N_ENT);
    float sum = 0.f, sq = 0.f;
    for (int r = r0; r < r1; r++) {
        float s = g_s2[r];
        float S = s / (s + 1e-16f);
        float val = g_agg2[(size_t)r * 256 + ct] + g_X12[(size_t)r * 512 + ct] * S;
        val = (val > 0.f) ? val : expm1f(val);
        val += g_ENT[(size_t)r * 256 + ct];
        out[(size_t)r * 256 + ct] = val;
        sum += val;
        sq += val * val;
    }
    atomicAdd(&g_csum[ct], sum);
    atomicAdd(&g_csq[ct], sq);
}

__global__ void bn_norm(float* __restrict__ out, const float* __restrict__ gamma,
                        const float* __restrict__ beta) {
    size_t gid = (size_t)blockIdx.x * blockDim.x + threadIdx.x;
    if (gid >= (size_t)N_ENT * 256) return;
    int d = (int)(gid & 255);
    float mu = g_csum[d] * (1.0f / N_ENT);
    float var = g_csq[d] * (1.0f / N_ENT) - mu * mu;
    float inv = rsqrtf(var + 1e-5f);
    out[gid] = (out[gid] - mu) * inv * gamma[d] + beta[d];
}

__global__ void copy_r(float* __restrict__ out) {
    int gid = blockIdx.x * blockDim.x + threadIdx.x;
    if (gid < N_REL * 256) out[(size_t)N_ENT * 256 + gid] = g_r[gid];
}

// ---------------- host orchestration ---------------------------------------
static void sgemm(const float* A, const float* B, float* C, int M, int N, int K) {
    dim3 grid(N / 128, (M + 127) / 128);
    sgemm_kernel<<<grid, 256>>>(M, N, K, A, B, C);
}

extern "C" void kernel_launch(void* const* d_in, const int* in_sizes, int n_in,
                              void* d_out, int out_size) {
    const int*   edge_index = (const int*)d_in[0];
    const int*   edge_type  = (const int*)d_in[1];
    const int*   ind2       = (const int*)d_in[2];
    const float* init_embed = (const float*)d_in[3];
    const float* init_rel   = (const float*)d_in[4];
    const float* W_heads    = (const float*)d_in[5];
    const float* a_heads    = (const float*)d_in[6];
    const float* gat_W      = (const float*)d_in[7];
    const float* out_W      = (const float*)d_in[8];
    const float* out_a      = (const float*)d_in[9];
    const float* W_entities = (const float*)d_in[10];
    const float* bn_gamma   = (const float*)d_in[11];
    const float* bn_beta    = (const float*)d_in[12];
    float* out = (float*)d_out;

    float *pAB, *pCrel, *pAgg1, *pX12, *pR3, *pEnt, *pR, *pW1ab, *pW1e, *pW2ab;
    cudaGetSymbolAddress((void**)&pAB, g_AB);
    cudaGetSymbolAddress((void**)&pCrel, g_Crel);
    cudaGetSymbolAddress((void**)&pAgg1, g_agg1);
    cudaGetSymbolAddress((void**)&pX12, g_X12);
    cudaGetSymbolAddress((void**)&pR3, g_R3);
    cudaGetSymbolAddress((void**)&pEnt, g_ENT);
    cudaGetSymbolAddress((void**)&pR, g_r);
    cudaGetSymbolAddress((void**)&pW1ab, g_W1ab);
    cudaGetSymbolAddress((void**)&pW1e, g_W1e);
    cudaGetSymbolAddress((void**)&pW2ab, g_W2ab);

    zero_kernel<<<2048, 256>>>();
    pack_w1<<<256, 256>>>(W_heads);
    pack_w2<<<512, 256>>>(out_W);

    // GEMMs independent of edge data
    sgemm(init_rel, gat_W, pR, N_REL, 256, 128);              // r
    sgemm(init_embed, pW1ab, pAB, N_ENT, 512, 128);           // A|B
    sgemm(init_rel, pW1e, pCrel, N_REL, 256, 128);            // Crel
    sgemm(init_embed, W_entities, pEnt, N_ENT, 256, 128);     // ENT

    dots_ab<<<5000, 256>>>(a_heads);
    dots_c<<<8, 256>>>(a_heads);

    // layer 1
    edge_logits1<<<(E_TOT + 255) / 256, 256>>>(edge_index, edge_type, ind2);
    edge_scatter1<<<E_TOT / 8, 256>>>(edge_index, edge_type, ind2);
    finalize1<<<(N_ENT * 256 + 255) / 256, 256>>>();

    // layer 2 precompute
    sgemm(pAgg1, pW2ab, pX12, N_ENT, 512, 256);               // X1|X2
    sgemm(pR, out_W + 512 * 256, pR3, N_REL, 256, 256);       // R3
    dots_x<<<10000, 256>>>(out_a);
    dots_r<<<(N_REL * 32 + 255) / 256, 256>>>(out_a);

    // layer 2 edges
    edge_logits2<<<(E_TOT + 255) / 256, 256>>>(edge_index, edge_type, ind2);
    edge_scatter2<<<E_TOT / 8, 256>>>(edge_index, edge_type, ind2);

    // epilogue: elu + residual + batchnorm, and r output
    finalize2_bn<<<(N_ENT + ROWS_PER_BLK - 1) / ROWS_PER_BLK, 256>>>(out);
    bn_norm<<<(N_ENT * 256 + 255) / 256, 256>>>(out, bn_gamma, bn_beta);
    copy_r<<<(N_REL * 256 + 255) / 256, 256>>>(out);
}

// round 7
// speedup vs baseline: 1.5233x; 1.5233x over previous
#include <cuda_runtime.h>
#include <math.h>

#define N_ENT   40000
#define N_REL   500
#define E_DIRN  200000
#define E_2HOP  50000
#define E_TOT   250000
#define D_IN    128
#define D_EMB   256

// ---------------- scratch (device globals; no allocation allowed) ----------
__device__ __align__(16) float g_ABE[(size_t)N_ENT * 768];     // [A(256)|B(256)|ENT(256)] per entity
__device__ __align__(16) float g_rC[N_REL * 512];              // [r(256)|Crel(256)] per relation
__device__ float g_aA[N_ENT * 4];
__device__ float g_aB[N_ENT * 4];
__device__ float g_aC[N_REL * 4];
__device__ float g_s1[N_ENT * 4];                              // softmax denominators layer1
__device__ __align__(16) float g_agg1[(size_t)N_ENT * 256];    // Σ w·v layer1 -> x (in place)
__device__ __align__(16) float g_X12[(size_t)N_ENT * 512];     // [X1 | X2] layer2
__device__ __align__(16) float g_R3[N_REL * 256];              // r @ out_W[512:]
__device__ float g_bx1[N_ENT];
__device__ float g_bx2[N_ENT];
__device__ float g_bR[N_REL];
__device__ float g_s2[N_ENT];
__device__ __align__(16) float g_agg2[(size_t)N_ENT * 256];
__device__ __align__(16) float g_W1E[128 * 768];               // packed layer1 [row|col|W_entities]
__device__ __align__(16) float g_WrC[128 * 512];               // packed [gat_W | W1edge]
__device__ __align__(16) float g_W2ab[256 * 512];              // packed layer2 [row|col] weights
__device__ float g_csum[256];
__device__ float g_csq[256];

// ---------------- helpers ---------------------------------------------------
__device__ __forceinline__ void red_add_v4(float* p, float4 v) {
    asm volatile("red.global.add.v4.f32 [%0], {%1,%2,%3,%4};"
                 :: "l"(p), "f"(v.x), "f"(v.y), "f"(v.z), "f"(v.w) : "memory");
}

// ---------------- zero scratch (must be re-zeroed every replay) ------------
__global__ void zero_kernel() {
    size_t i = (size_t)blockIdx.x * blockDim.x + threadIdx.x;
    size_t stride = (size_t)gridDim.x * blockDim.x;
    for (size_t k = i; k < (size_t)N_ENT * 256; k += stride) { g_agg1[k] = 0.f; g_agg2[k] = 0.f; }
    for (size_t k = i; k < (size_t)N_ENT * 4; k += stride) g_s1[k] = 0.f;
    for (size_t k = i; k < (size_t)N_ENT; k += stride) g_s2[k] = 0.f;
    if (i < 256) { g_csum[i] = 0.f; g_csq[i] = 0.f; }
}

// ---------------- weight packing -------------------------------------------
// W_heads: (4, 384, 64) row-major.
// g_W1E[k*768+j]:
//   j<256:    head h=j/64, col c=j%64, W_heads row k        (× init_embed[row])
//   256..511: W_heads row 128+k                              (× init_embed[col])
//   512..767: W_entities[k*256 + (j-512)]
__global__ void pack_w1E(const float* __restrict__ W_heads, const float* __restrict__ W_entities) {
    int gid = blockIdx.x * blockDim.x + threadIdx.x;
    int stride = gridDim.x * blockDim.x;
    for (int idx = gid; idx < 128 * 768; idx += stride) {
        int k = idx / 768, j = idx % 768;
        float v;
        if (j < 512) {
            int part = (j < 256) ? 0 : 1;
            int jj = j & 255;
            int h = jj >> 6, c = jj & 63;
            v = W_heads[h * (384 * 64) + (part * 128 + k) * 64 + c];
        } else {
            v = W_entities[k * 256 + (j - 512)];
        }
        g_W1E[idx] = v;
    }
}

// g_WrC[k*512+j]: j<256: gat_W[k*256+j]; j>=256: W_heads row 256+k (edge part)
__global__ void pack_wrC(const float* __restrict__ gat_W, const float* __restrict__ W_heads) {
    int gid = blockIdx.x * blockDim.x + threadIdx.x;
    int stride = gridDim.x * blockDim.x;
    for (int idx = gid; idx < 128 * 512; idx += stride) {
        int k = idx >> 9, j = idx & 511;
        float v;
        if (j < 256) {
            v = gat_W[k * 256 + j];
        } else {
            int jj = j - 256;
            int h = jj >> 6, c = jj & 63;
            v = W_heads[h * (384 * 64) + (256 + k) * 64 + c];
        }
        g_WrC[idx] = v;
    }
}

// out_W: (768, 256). g_W2ab[k*512+j] = out_W[(j<256 ? k : 256+k)*256 + (j%256)]
__global__ void pack_w2(const float* __restrict__ out_W) {
    int gid = blockIdx.x * blockDim.x + threadIdx.x;
    int stride = gridDim.x * blockDim.x;
    for (int idx = gid; idx < 256 * 512; idx += stride) {
        int k = idx >> 9, j = idx & 511;
        int src_row = (j < 256) ? k : (256 + k);
        g_W2ab[idx] = out_W[src_row * 256 + (j & 255)];
    }
}

// ---------------- SGEMM: C[MxN] = A[MxK] @ B[KxN], with leading dims -------
// N % 128 == 0, K % 8 == 0; arbitrary M.
__global__ __launch_bounds__(256, 2) void sgemm_kernel(
    int M, int N, int K, int lda, int ldb, int ldc,
    const float* __restrict__ A, const float* __restrict__ B, float* __restrict__ C)
{
    const int BM = 128, BN = 128, BK = 8, TM = 8, TN = 8;
    __shared__ float As[BK][BM];
    __shared__ float Bs[BK][BN];
    const int tid = threadIdx.x;
    const int crow = (tid / (BN / TN)) * TM;
    const int ccol = (tid % (BN / TN)) * TN;
    const int mBase = blockIdx.y * BM;
    const int nBase = blockIdx.x * BN;
    const int aRow = tid >> 1;
    const int aCol = (tid & 1) * 4;
    const int bRow = tid >> 5;
    const int bCol = (tid & 31) * 4;

    const float* Ap = A + (size_t)mBase * lda;
    const float* Bp = B + nBase;
    float* Cp = C + (size_t)mBase * ldc + nBase;

    float acc[TM][TN];
#pragma unroll
    for (int i = 0; i < TM; i++)
#pragma unroll
        for (int j = 0; j < TN; j++) acc[i][j] = 0.f;

    for (int k0 = 0; k0 < K; k0 += BK) {
        float4 av;
        if (mBase + aRow < M)
            av = *(const float4*)&Ap[(size_t)aRow * lda + k0 + aCol];
        else
            av = make_float4(0.f, 0.f, 0.f, 0.f);
        As[aCol + 0][aRow] = av.x;
        As[aCol + 1][aRow] = av.y;
        As[aCol + 2][aRow] = av.z;
        As[aCol + 3][aRow] = av.w;
        float4 bv = *(const float4*)&Bp[(size_t)(k0 + bRow) * ldb + bCol];
        *(float4*)&Bs[bRow][bCol] = bv;
        __syncthreads();
#pragma unroll
        for (int k = 0; k < BK; k++) {
            float4 ra0 = *(const float4*)&As[k][crow];
            float4 ra1 = *(const float4*)&As[k][crow + 4];
            float4 rb0 = *(const float4*)&Bs[k][ccol];
            float4 rb1 = *(const float4*)&Bs[k][ccol + 4];
            float ra[TM] = {ra0.x, ra0.y, ra0.z, ra0.w, ra1.x, ra1.y, ra1.z, ra1.w};
            float rb[TN] = {rb0.x, rb0.y, rb0.z, rb0.w, rb1.x, rb1.y, rb1.z, rb1.w};
#pragma unroll
            for (int i = 0; i < TM; i++)
#pragma unroll
                for (int j = 0; j < TN; j++) acc[i][j] += ra[i] * rb[j];
        }
        __syncthreads();
    }
#pragma unroll
    for (int i = 0; i < TM; i++) {
        if (mBase + crow + i < M) {
            *(float4*)&Cp[(size_t)(crow + i) * ldc + ccol]     = make_float4(acc[i][0], acc[i][1], acc[i][2], acc[i][3]);
            *(float4*)&Cp[(size_t)(crow + i) * ldc + ccol + 4] = make_float4(acc[i][4], acc[i][5], acc[i][6], acc[i][7]);
        }
    }
}

// ---------------- small-M SGEMM (M ~ 500): 16x128 tiles --------------------
__global__ __launch_bounds__(256) void sgemm_small_kernel(
    int M, int N, int K, int lda, int ldb, int ldc,
    const float* __restrict__ A, const float* __restrict__ B, float* __restrict__ C)
{
    const int BM = 16, BN = 128, BK = 16;
    __shared__ float As[BM][BK];
    __shared__ float Bs[BK][BN];
    const int tid = threadIdx.x;
    const int r = tid >> 4;           // 0..15  (row in tile)
    const int c = (tid & 15) * 8;     // col group
    const int mBase = blockIdx.y * BM;
    const int nBase = blockIdx.x * BN;
    const int bRow = tid >> 4;        // 0..15
    const int bCol = (tid & 15) * 8;

    float acc[8];
#pragma unroll
    for (int j = 0; j < 8; j++) acc[j] = 0.f;

    for (int k0 = 0; k0 < K; k0 += BK) {
        int arow = tid >> 4, acol = tid & 15;
        As[arow][acol] = (mBase + arow < M) ? A[(size_t)(mBase + arow) * lda + k0 + acol] : 0.f;
        *(float4*)&Bs[bRow][bCol]     = *(const float4*)&B[(size_t)(k0 + bRow) * ldb + nBase + bCol];
        *(float4*)&Bs[bRow][bCol + 4] = *(const float4*)&B[(size_t)(k0 + bRow) * ldb + nBase + bCol + 4];
        __syncthreads();
#pragma unroll
        for (int k = 0; k < BK; k++) {
            float a = As[r][k];
            float4 b0 = *(const float4*)&Bs[k][c];
            float4 b1 = *(const float4*)&Bs[k][c + 4];
            acc[0] += a * b0.x; acc[1] += a * b0.y; acc[2] += a * b0.z; acc[3] += a * b0.w;
            acc[4] += a * b1.x; acc[5] += a * b1.y; acc[6] += a * b1.z; acc[7] += a * b1.w;
        }
        __syncthreads();
    }
    if (mBase + r < M) {
        float* Cp = C + (size_t)(mBase + r) * ldc + nBase + c;
        *(float4*)Cp       = make_float4(acc[0], acc[1], acc[2], acc[3]);
        *(float4*)(Cp + 4) = make_float4(acc[4], acc[5], acc[6], acc[7]);
    }
}

// ---------------- scalar projections ---------------------------------------
__global__ void dots_ab(const float* __restrict__ a_heads) {
    int w = (blockIdx.x * blockDim.x + threadIdx.x) >> 5;
    int lane = threadIdx.x & 31;
    if (w >= N_ENT) return;
    const float* p = g_ABE + (size_t)w * 768;
#pragma unroll
    for (int h = 0; h < 4; h++) {
        float a0 = a_heads[h * 64 + lane];
        float a1 = a_heads[h * 64 + 32 + lane];
        float sA = p[h * 64 + lane] * a0 + p[h * 64 + 32 + lane] * a1;
        float sB = p[256 + h * 64 + lane] * a0 + p[256 + h * 64 + 32 + lane] * a1;
#pragma unroll
        for (int o = 16; o; o >>= 1) {
            sA += __shfl_xor_sync(0xffffffffu, sA, o);
            sB += __shfl_xor_sync(0xffffffffu, sB, o);
        }
        if (lane == 0) { g_aA[w * 4 + h] = sA; g_aB[w * 4 + h] = sB; }
    }
}

__global__ void dots_c(const float* __restrict__ a_heads) {
    int t = blockIdx.x * blockDim.x + threadIdx.x;
    if (t >= N_REL * 4) return;
    int r = t >> 2, h = t & 3;
    float s = 0.f;
    for (int j = 0; j < 64; j++) s += g_rC[r * 512 + 256 + h * 64 + j] * a_heads[h * 64 + j];
    g_aC[t] = s;
}

__global__ void dots_x(const float* __restrict__ out_a) {
    int w = (blockIdx.x * blockDim.x + threadIdx.x) >> 5;
    int lane = threadIdx.x & 31;
    if (w >= 2 * N_ENT) return;
    int i = w >> 1, sel = w & 1;
    const float* p = g_X12 + (size_t)i * 512 + sel * 256;
    float s = 0.f;
    for (int d = lane; d < 256; d += 32) s += p[d] * out_a[d];
#pragma unroll
    for (int o = 16; o; o >>= 1) s += __shfl_xor_sync(0xffffffffu, s, o);
    if (lane == 0) { if (sel) g_bx2[i] = s; else g_bx1[i] = s; }
}

__global__ void dots_r(const float* __restrict__ out_a) {
    int w = (blockIdx.x * blockDim.x + threadIdx.x) >> 5;
    int lane = threadIdx.x & 31;
    if (w >= N_REL) return;
    float s = 0.f;
    for (int d = lane; d < 256; d += 32) s += g_R3[w * 256 + d] * out_a[d];
#pragma unroll
    for (int o = 16; o; o >>= 1) s += __shfl_xor_sync(0xffffffffu, s, o);
    if (lane == 0) g_bR[w] = s;
}

// ---------------- layer 1 fused logits+scatter (unnormalized) --------------
// one warp per edge: compute w_h = exp(lrelu(logit_h)), atomically accumulate
// denominators, and scatter w_h * (B[col]+Crel) into g_agg1 with vector REDs.
__global__ void edge_fused1(const int* __restrict__ ei, const int* __restrict__ et,
                            const int* __restrict__ i2) {
    int e = (blockIdx.x * blockDim.x + threadIdx.x) >> 5;
    int lane = threadIdx.x & 31;
    if (e >= E_TOT) return;
    int row, col;
    const float* C0;
    const float* C1 = nullptr;
    float cadd;
    int h = lane >> 3;                 // 8 dims per lane stay within one head
    if (e < E_DIRN) {
        row = ei[E_DIRN + e];
        col = ei[e];
        int t = et[e];
        C0 = g_rC + t * 512 + 256;
        cadd = g_aC[t * 4 + h];
    } else {
        int q = (e - E_DIRN) * 4;
        row = i2[q + 3]; col = i2[q + 0];
        int t0 = i2[q + 1], t1 = i2[q + 2];
        C0 = g_rC + t0 * 512 + 256;
        C1 = g_rC + t1 * 512 + 256;
        cadd = g_aC[t0 * 4 + h] + g_aC[t1 * 4 + h];
    }
    float l = g_aA[row * 4 + h] + g_aB[col * 4 + h] + cadd;
    l = (l > 0.f) ? l : 0.2f * l;      // leaky_relu
    float w = expf(l);                 // logits O(1): no max-shift needed
    if ((lane & 7) == 0) atomicAdd(&g_s1[row * 4 + h], w);

    int d = lane * 8;
    const float* Bp = g_ABE + (size_t)col * 768 + 256;
    float* Ap = g_agg1 + (size_t)row * 256;
    float4 v0 = *(const float4*)(Bp + d);
    float4 v1 = *(const float4*)(Bp + d + 4);
    float4 c0 = *(const float4*)(C0 + d);
    float4 c1 = *(const float4*)(C0 + d + 4);
    v0.x += c0.x; v0.y += c0.y; v0.z += c0.z; v0.w += c0.w;
    v1.x += c1.x; v1.y += c1.y; v1.z += c1.z; v1.w += c1.w;
    if (C1) {
        float4 e0 = *(const float4*)(C1 + d);
        float4 e1 = *(const float4*)(C1 + d + 4);
        v0.x += e0.x; v0.y += e0.y; v0.z += e0.z; v0.w += e0.w;
        v1.x += e1.x; v1.y += e1.y; v1.z += e1.z; v1.w += e1.w;
    }
    v0.x *= w; v0.y *= w; v0.z *= w; v0.w *= w;
    v1.x *= w; v1.y *= w; v1.z *= w; v1.w *= w;
    red_add_v4(Ap + d, v0);
    red_add_v4(Ap + d + 4, v1);
}

// x = elu((aggw + A[v]*s) / (s + 1e-16))
__global__ void finalize1() {
    size_t gid = (size_t)blockIdx.x * blockDim.x + threadIdx.x;
    if (gid >= (size_t)N_ENT * 256) return;
    int v = (int)(gid >> 8);
    int d = (int)(gid & 255);
    int h = d >> 6;
    float s = g_s1[v * 4 + h];
    float val = (g_agg1[gid] + g_ABE[(size_t)v * 768 + d] * s) / (s + 1e-16f);
    g_agg1[gid] = (val > 0.f) ? val : expm1f(val);
}

// ---------------- layer 2 fused logits+scatter ------------------------------
__global__ void edge_fused2(const int* __restrict__ ei, const int* __restrict__ et,
                            const int* __restrict__ i2) {
    int e = (blockIdx.x * blockDim.x + threadIdx.x) >> 5;
    int lane = threadIdx.x & 31;
    if (e >= E_TOT) return;
    int row, col;
    const float* C0;
    const float* C1 = nullptr;
    float cadd;
    if (e < E_DIRN) {
        row = ei[E_DIRN + e]; col = ei[e];
        int t = et[e];
        C0 = g_R3 + t * 256;
        cadd = g_bR[t];
    } else {
        int q = (e - E_DIRN) * 4;
        row = i2[q + 3]; col = i2[q + 0];
        int t0 = i2[q + 1], t1 = i2[q + 2];
        C0 = g_R3 + t0 * 256;
        C1 = g_R3 + t1 * 256;
        cadd = g_bR[t0] + g_bR[t1];
    }
    float l = g_bx1[row] + g_bx2[col] + cadd;
    l = (l > 0.f) ? l : 0.2f * l;
    float w = expf(l);
    if (lane == 0) atomicAdd(&g_s2[row], w);

    int d = lane * 8;
    const float* Xp = g_X12 + (size_t)col * 512 + 256;   // X2 half
    float* Ap = g_agg2 + (size_t)row * 256;
    float4 v0 = *(const float4*)(Xp + d);
    float4 v1 = *(const float4*)(Xp + d + 4);
    float4 c0 = *(const float4*)(C0 + d);
    float4 c1 = *(const float4*)(C0 + d + 4);
    v0.x += c0.x; v0.y += c0.y; v0.z += c0.z; v0.w += c0.w;
    v1.x += c1.x; v1.y += c1.y; v1.z += c1.z; v1.w += c1.w;
    if (C1) {
        float4 e0 = *(const float4*)(C1 + d);
        float4 e1 = *(const float4*)(C1 + d + 4);
        v0.x += e0.x; v0.y += e0.y; v0.z += e0.z; v0.w += e0.w;
        v1.x += e1.x; v1.y += e1.y; v1.z += e1.z; v1.w += e1.w;
    }
    v0.x *= w; v0.y *= w; v0.z *= w; v0.w *= w;
    v1.x *= w; v1.y *= w; v1.z *= w; v1.w *= w;
    red_add_v4(Ap + d, v0);
    red_add_v4(Ap + d + 4, v1);
}

// out = elu((aggw2 + X1[v]*s)/(s+eps)) + ENT[v]; accumulate column sum/sumsq
#define ROWS_PER_BLK 128
__global__ void finalize2_bn(float* __restrict__ out) {
    int ct = threadIdx.x;                        // column 0..255
    int r0 = blockIdx.x * ROWS_PER_BLK;
    int r1 = min(r0 + ROWS_PER_BLK, N_ENT);
    float sum = 0.f, sq = 0.f;
    for (int r = r0; r < r1; r++) {
        float s = g_s2[r];
        float val = (g_agg2[(size_t)r * 256 + ct] + g_X12[(size_t)r * 512 + ct] * s) / (s + 1e-16f);
        val = (val > 0.f) ? val : expm1f(val);
        val += g_ABE[(size_t)r * 768 + 512 + ct];
        out[(size_t)r * 256 + ct] = val;
        sum += val;
        sq += val * val;
    }
    atomicAdd(&g_csum[ct], sum);
    atomicAdd(&g_csq[ct], sq);
}

__global__ void bn_norm(float* __restrict__ out, const float* __restrict__ gamma,
                        const float* __restrict__ beta) {
    size_t gid = (size_t)blockIdx.x * blockDim.x + threadIdx.x;
    if (gid >= (size_t)N_ENT * 256) return;
    int d = (int)(gid & 255);
    float mu = g_csum[d] * (1.0f / N_ENT);
    float var = g_csq[d] * (1.0f / N_ENT) - mu * mu;
    float inv = rsqrtf(var + 1e-5f);
    out[gid] = (out[gid] - mu) * inv * gamma[d] + beta[d];
}

__global__ void copy_r(float* __restrict__ out) {
    int gid = blockIdx.x * blockDim.x + threadIdx.x;
    if (gid < N_REL * 256)
        out[(size_t)N_ENT * 256 + gid] = g_rC[(gid >> 8) * 512 + (gid & 255)];
}

// ---------------- host orchestration ---------------------------------------
static void sgemm(const float* A, const float* B, float* C, int M, int N, int K,
                  int lda, int ldb, int ldc) {
    dim3 grid(N / 128, (M + 127) / 128);
    sgemm_kernel<<<grid, 256>>>(M, N, K, lda, ldb, ldc, A, B, C);
}
static void sgemm_small(const float* A, const float* B, float* C, int M, int N, int K,
                        int lda, int ldb, int ldc) {
    dim3 grid(N / 128, (M + 15) / 16);
    sgemm_small_kernel<<<grid, 256>>>(M, N, K, lda, ldb, ldc, A, B, C);
}

extern "C" void kernel_launch(void* const* d_in, const int* in_sizes, int n_in,
                              void* d_out, int out_size) {
    const int*   edge_index = (const int*)d_in[0];
    const int*   edge_type  = (const int*)d_in[1];
    const int*   ind2       = (const int*)d_in[2];
    const float* init_embed = (const float*)d_in[3];
    const float* init_rel   = (const float*)d_in[4];
    const float* W_heads    = (const float*)d_in[5];
    const float* a_heads    = (const float*)d_in[6];
    const float* gat_W      = (const float*)d_in[7];
    const float* out_W      = (const float*)d_in[8];
    const float* out_a      = (const float*)d_in[9];
    const float* W_entities = (const float*)d_in[10];
    const float* bn_gamma   = (const float*)d_in[11];
    const float* bn_beta    = (const float*)d_in[12];
    float* out = (float*)d_out;

    float *pABE, *prC, *pAgg1, *pX12, *pR3, *pW1E, *pWrC, *pW2ab;
    cudaGetSymbolAddress((void**)&pABE, g_ABE);
    cudaGetSymbolAddress((void**)&prC, g_rC);
    cudaGetSymbolAddress((void**)&pAgg1, g_agg1);
    cudaGetSymbolAddress((void**)&pX12, g_X12);
    cudaGetSymbolAddress((void**)&pR3, g_R3);
    cudaGetSymbolAddress((void**)&pW1E, g_W1E);
    cudaGetSymbolAddress((void**)&pWrC, g_WrC);
    cudaGetSymbolAddress((void**)&pW2ab, g_W2ab);

    // launch index:                                                    (ncu -s 5 -c 1
    zero_kernel<<<2048, 256>>>();                                    // 0  captures #5:
    pack_w1E<<<384, 256>>>(W_heads, W_entities);                     // 1  the big GEMM)
    pack_w2<<<512, 256>>>(out_W);                                    // 2
    pack_wrC<<<256, 256>>>(gat_W, W_heads);                          // 3
    sgemm_small(init_rel, pWrC, prC, N_REL, 512, 128, 128, 512, 512);// 4  [r|Crel]
    sgemm(init_embed, pW1E, pABE, N_ENT, 768, 128, 128, 768, 768);   // 5  [A|B|ENT]

    dots_ab<<<5000, 256>>>(a_heads);
    dots_c<<<8, 256>>>(a_heads);

    // layer 1 (fused logits + unnormalized scatter)
    edge_fused1<<<E_TOT / 8, 256>>>(edge_index, edge_type, ind2);
    finalize1<<<(N_ENT * 256 + 255) / 256, 256>>>();

    // layer 2 precompute
    sgemm(pAgg1, pW2ab, pX12, N_ENT, 512, 256, 256, 512, 512);       // [X1|X2]
    sgemm_small(prC, out_W + 512 * 256, pR3, N_REL, 256, 256, 512, 256, 256); // R3
    dots_x<<<10000, 256>>>(out_a);
    dots_r<<<(N_REL * 32 + 255) / 256, 256>>>(out_a);

    // layer 2
    edge_fused2<<<E_TOT / 8, 256>>>(edge_index, edge_type, ind2);

    // epilogue: elu + residual + batchnorm, and r output
    finalize2_bn<<<(N_ENT + ROWS_PER_BLK - 1) / ROWS_PER_BLK, 256>>>(out);
    bn_norm<<<(N_ENT * 256 + 255) / 256, 256>>>(out, bn_gamma, bn_beta);
    copy_r<<<(N_REL * 256 + 255) / 256, 256>>>(out);
}

// round 9
// speedup vs baseline: 2.2037x; 1.4467x over previous
#include <cuda_runtime.h>
#include <math.h>
#include <stdint.h>

#define N_ENT   40000
#define N_REL   500
#define E_DIRN  200000
#define E_2HOP  50000
#define E_TOT   250000
#define D_IN    128
#define D_EMB   256

// ---------------- scratch (device globals; no allocation allowed) ----------
__device__ __align__(16) float g_ABE[(size_t)N_ENT * 768];     // [A(256)|B(256)|ENT(256)] per entity
__device__ __align__(16) float g_rC[N_REL * 512];              // [r(256)|Crel(256)] per relation
__device__ float g_aA[N_ENT * 4];
__device__ float g_aB[N_ENT * 4];
__device__ float g_aC[N_REL * 4];
__device__ float g_s1[N_ENT * 4];                              // softmax denominators layer1
__device__ __align__(16) float g_agg1[(size_t)N_ENT * 256];    // Σ w·v layer1 -> x (in place)
__device__ __align__(16) float g_X12[(size_t)N_ENT * 512];     // [X1 | X2] layer2
__device__ __align__(16) float g_R3[N_REL * 256];              // r @ out_W[512:]
__device__ float g_bx1[N_ENT];
__device__ float g_bx2[N_ENT];
__device__ float g_bR[N_REL];
__device__ float g_s2[N_ENT];
__device__ __align__(16) float g_agg2[(size_t)N_ENT * 256];
__device__ __align__(16) float g_W1E[128 * 768];               // packed layer1 [row|col|W_entities]
__device__ __align__(16) float g_WrC[128 * 512];               // packed [gat_W | W1edge]
__device__ __align__(16) float g_W2ab[256 * 512];              // packed layer2 [row|col] weights
__device__ float g_csum[256];
__device__ float g_csq[256];

// ---------------- helpers ---------------------------------------------------
__device__ __forceinline__ void red_add_v4(float* p, float4 v) {
    asm volatile("red.global.add.v4.f32 [%0], {%1,%2,%3,%4};"
                 :: "l"(p), "f"(v.x), "f"(v.y), "f"(v.z), "f"(v.w) : "memory");
}
__device__ __forceinline__ uint32_t f2tf32(float x) {
    uint32_t r;
    asm("cvt.rna.tf32.f32 %0, %1;" : "=r"(r) : "f"(x));
    return r;
}

// ---------------- zero scratch (must be re-zeroed every replay) ------------
__global__ void zero_kernel() {
    size_t i = (size_t)blockIdx.x * blockDim.x + threadIdx.x;
    size_t stride = (size_t)gridDim.x * blockDim.x;
    for (size_t k = i; k < (size_t)N_ENT * 256; k += stride) { g_agg1[k] = 0.f; g_agg2[k] = 0.f; }
    for (size_t k = i; k < (size_t)N_ENT * 4; k += stride) g_s1[k] = 0.f;
    for (size_t k = i; k < (size_t)N_ENT; k += stride) g_s2[k] = 0.f;
    if (i < 256) { g_csum[i] = 0.f; g_csq[i] = 0.f; }
}

// ---------------- weight packing -------------------------------------------
__global__ void pack_w1E(const float* __restrict__ W_heads, const float* __restrict__ W_entities) {
    int gid = blockIdx.x * blockDim.x + threadIdx.x;
    int stride = gridDim.x * blockDim.x;
    for (int idx = gid; idx < 128 * 768; idx += stride) {
        int k = idx / 768, j = idx % 768;
        float v;
        if (j < 512) {
            int part = (j < 256) ? 0 : 1;
            int jj = j & 255;
            int h = jj >> 6, c = jj & 63;
            v = W_heads[h * (384 * 64) + (part * 128 + k) * 64 + c];
        } else {
            v = W_entities[k * 256 + (j - 512)];
        }
        g_W1E[idx] = v;
    }
}

__global__ void pack_wrC(const float* __restrict__ gat_W, const float* __restrict__ W_heads) {
    int gid = blockIdx.x * blockDim.x + threadIdx.x;
    int stride = gridDim.x * blockDim.x;
    for (int idx = gid; idx < 128 * 512; idx += stride) {
        int k = idx >> 9, j = idx & 511;
        float v;
        if (j < 256) {
            v = gat_W[k * 256 + j];
        } else {
            int jj = j - 256;
            int h = jj >> 6, c = jj & 63;
            v = W_heads[h * (384 * 64) + (256 + k) * 64 + c];
        }
        g_WrC[idx] = v;
    }
}

__global__ void pack_w2(const float* __restrict__ out_W) {
    int gid = blockIdx.x * blockDim.x + threadIdx.x;
    int stride = gridDim.x * blockDim.x;
    for (int idx = gid; idx < 256 * 512; idx += stride) {
        int k = idx >> 9, j = idx & 511;
        int src_row = (j < 256) ? k : (256 + k);
        g_W2ab[idx] = out_W[src_row * 256 + (j & 255)];
    }
}

// ---------------- TF32 tensor-core GEMM ------------------------------------
// C[M,N] = A[M,K] @ B[K,N], row-major with leading dims.
// Requires N % 128 == 0, K % 16 == 0. Arbitrary M (guarded).
// Block tile 128x128x16, 8 warps (2x4), warp tile 64x32, mma.m16n8k8.tf32.
#define ASP 20      // As pitch (floats): (20*gr + kk) % 32 covers all banks
#define BSP 136     // Bs pitch: (136*kk + gr) % 32 = 8*kk + gr -> conflict-free

__global__ __launch_bounds__(256, 2) void tf32_gemm_kernel(
    int M, int N, int K, int lda, int ldb, int ldc,
    const float* __restrict__ A, const float* __restrict__ B, float* __restrict__ C)
{
    __shared__ uint32_t As[128 * ASP];   // [m][k], tf32-rounded
    __shared__ uint32_t Bs[16 * BSP];    // [k][n], tf32-rounded
    const int tid = threadIdx.x;
    const int lane = tid & 31;
    const int warp = tid >> 5;
    const int warpM = warp >> 2;         // 0..1
    const int warpN = warp & 3;          // 0..3
    const int mBase = blockIdx.y * 128;
    const int nBase = blockIdx.x * 128;
    const int gr = lane >> 2;            // group row 0..7
    const int tig = lane & 3;            // thread in group 0..3

    // global->shared thread mapping
    const int aRow = tid >> 2;           // 0..63 (and +64)
    const int aCol = (tid & 3) * 4;
    const int bRow = tid >> 5;           // 0..7 (and +8)
    const int bCol = (tid & 31) * 4;

    float acc[4][4][4];
#pragma unroll
    for (int i = 0; i < 4; i++)
#pragma unroll
        for (int j = 0; j < 4; j++)
#pragma unroll
            for (int f = 0; f < 4; f++) acc[i][j][f] = 0.f;

    for (int k0 = 0; k0 < K; k0 += 16) {
#pragma unroll
        for (int half = 0; half < 2; half++) {
            int r = aRow + half * 64;
            float4 v = (mBase + r < M)
                ? *(const float4*)&A[(size_t)(mBase + r) * lda + k0 + aCol]
                : make_float4(0.f, 0.f, 0.f, 0.f);
            uint4 u = make_uint4(f2tf32(v.x), f2tf32(v.y), f2tf32(v.z), f2tf32(v.w));
            *(uint4*)&As[r * ASP + aCol] = u;
        }
#pragma unroll
        for (int half = 0; half < 2; half++) {
            int r = bRow + half * 8;
            float4 v = *(const float4*)&B[(size_t)(k0 + r) * ldb + nBase + bCol];
            uint4 u = make_uint4(f2tf32(v.x), f2tf32(v.y), f2tf32(v.z), f2tf32(v.w));
            *(uint4*)&Bs[r * BSP + bCol] = u;
        }
        __syncthreads();

#pragma unroll
        for (int ks = 0; ks < 16; ks += 8) {
            uint32_t af[4][4], bf[4][2];
#pragma unroll
            for (int mt = 0; mt < 4; mt++) {
                int r = warpM * 64 + mt * 16 + gr;
                af[mt][0] = As[r * ASP + ks + tig];
                af[mt][1] = As[(r + 8) * ASP + ks + tig];
                af[mt][2] = As[r * ASP + ks + tig + 4];
                af[mt][3] = As[(r + 8) * ASP + ks + tig + 4];
            }
#pragma unroll
            for (int nt = 0; nt < 4; nt++) {
                int n = warpN * 32 + nt * 8 + gr;
                bf[nt][0] = Bs[(ks + tig) * BSP + n];
                bf[nt][1] = Bs[(ks + tig + 4) * BSP + n];
            }
#pragma unroll
            for (int mt = 0; mt < 4; mt++)
#pragma unroll
                for (int nt = 0; nt < 4; nt++) {
                    asm volatile(
                        "mma.sync.aligned.m16n8k8.row.col.f32.tf32.tf32.f32 "
                        "{%0,%1,%2,%3}, {%4,%5,%6,%7}, {%8,%9}, {%0,%1,%2,%3};"
                        : "+f"(acc[mt][nt][0]), "+f"(acc[mt][nt][1]),
                          "+f"(acc[mt][nt][2]), "+f"(acc[mt][nt][3])
                        : "r"(af[mt][0]), "r"(af[mt][1]), "r"(af[mt][2]), "r"(af[mt][3]),
                          "r"(bf[nt][0]), "r"(bf[nt][1]));
                }
        }
        __syncthreads();
    }

    // store C
#pragma unroll
    for (int mt = 0; mt < 4; mt++) {
        int r0 = mBase + warpM * 64 + mt * 16 + gr;
#pragma unroll
        for (int nt = 0; nt < 4; nt++) {
            int c = nBase + warpN * 32 + nt * 8 + 2 * tig;
            if (r0 < M)
                *(float2*)&C[(size_t)r0 * ldc + c] = make_float2(acc[mt][nt][0], acc[mt][nt][1]);
            if (r0 + 8 < M)
                *(float2*)&C[(size_t)(r0 + 8) * ldc + c] = make_float2(acc[mt][nt][2], acc[mt][nt][3]);
        }
    }
}

// ---------------- small-M SGEMM (M ~ 500): 16x128 tiles --------------------
__global__ __launch_bounds__(256) void sgemm_small_kernel(
    int M, int N, int K, int lda, int ldb, int ldc,
    const float* __restrict__ A, const float* __restrict__ B, float* __restrict__ C)
{
    const int BM = 16, BN = 128, BK = 16;
    __shared__ float As[BM][BK];
    __shared__ float Bs[BK][BN];
    const int tid = threadIdx.x;
    const int r = tid >> 4;
    const int c = (tid & 15) * 8;
    const int mBase = blockIdx.y * BM;
    const int nBase = blockIdx.x * BN;
    const int bRow = tid >> 4;
    const int bCol = (tid & 15) * 8;

    float acc[8];
#pragma unroll
    for (int j = 0; j < 8; j++) acc[j] = 0.f;

    for (int k0 = 0; k0 < K; k0 += BK) {
        int arow = tid >> 4, acol = tid & 15;
        As[arow][acol] = (mBase + arow < M) ? A[(size_t)(mBase + arow) * lda + k0 + acol] : 0.f;
        *(float4*)&Bs[bRow][bCol]     = *(const float4*)&B[(size_t)(k0 + bRow) * ldb + nBase + bCol];
        *(float4*)&Bs[bRow][bCol + 4] = *(const float4*)&B[(size_t)(k0 + bRow) * ldb + nBase + bCol + 4];
        __syncthreads();
#pragma unroll
        for (int k = 0; k < BK; k++) {
            float a = As[r][k];
            float4 b0 = *(const float4*)&Bs[k][c];
            float4 b1 = *(const float4*)&Bs[k][c + 4];
            acc[0] += a * b0.x; acc[1] += a * b0.y; acc[2] += a * b0.z; acc[3] += a * b0.w;
            acc[4] += a * b1.x; acc[5] += a * b1.y; acc[6] += a * b1.z; acc[7] += a * b1.w;
        }
        __syncthreads();
    }
    if (mBase + r < M) {
        float* Cp = C + (size_t)(mBase + r) * ldc + nBase + c;
        *(float4*)Cp       = make_float4(acc[0], acc[1], acc[2], acc[3]);
        *(float4*)(Cp + 4) = make_float4(acc[4], acc[5], acc[6], acc[7]);
    }
}

// ---------------- scalar projections ---------------------------------------
__global__ void dots_ab(const float* __restrict__ a_heads) {
    int w = (blockIdx.x * blockDim.x + threadIdx.x) >> 5;
    int lane = threadIdx.x & 31;
    if (w >= N_ENT) return;
    const float* p = g_ABE + (size_t)w * 768;
#pragma unroll
    for (int h = 0; h < 4; h++) {
        float a0 = a_heads[h * 64 + lane];
        float a1 = a_heads[h * 64 + 32 + lane];
        float sA = p[h * 64 + lane] * a0 + p[h * 64 + 32 + lane] * a1;
        float sB = p[256 + h * 64 + lane] * a0 + p[256 + h * 64 + 32 + lane] * a1;
#pragma unroll
        for (int o = 16; o; o >>= 1) {
            sA += __shfl_xor_sync(0xffffffffu, sA, o);
            sB += __shfl_xor_sync(0xffffffffu, sB, o);
        }
        if (lane == 0) { g_aA[w * 4 + h] = sA; g_aB[w * 4 + h] = sB; }
    }
}

__global__ void dots_c(const float* __restrict__ a_heads) {
    int t = blockIdx.x * blockDim.x + threadIdx.x;
    if (t >= N_REL * 4) return;
    int r = t >> 2, h = t & 3;
    float s = 0.f;
    for (int j = 0; j < 64; j++) s += g_rC[r * 512 + 256 + h * 64 + j] * a_heads[h * 64 + j];
    g_aC[t] = s;
}

__global__ void dots_x(const float* __restrict__ out_a) {
    int w = (blockIdx.x * blockDim.x + threadIdx.x) >> 5;
    int lane = threadIdx.x & 31;
    if (w >= 2 * N_ENT) return;
    int i = w >> 1, sel = w & 1;
    const float* p = g_X12 + (size_t)i * 512 + sel * 256;
    float s = 0.f;
    for (int d = lane; d < 256; d += 32) s += p[d] * out_a[d];
#pragma unroll
    for (int o = 16; o; o >>= 1) s += __shfl_xor_sync(0xffffffffu, s, o);
    if (lane == 0) { if (sel) g_bx2[i] = s; else g_bx1[i] = s; }
}

__global__ void dots_r(const float* __restrict__ out_a) {
    int w = (blockIdx.x * blockDim.x + threadIdx.x) >> 5;
    int lane = threadIdx.x & 31;
    if (w >= N_REL) return;
    float s = 0.f;
    for (int d = lane; d < 256; d += 32) s += g_R3[w * 256 + d] * out_a[d];
#pragma unroll
    for (int o = 16; o; o >>= 1) s += __shfl_xor_sync(0xffffffffu, s, o);
    if (lane == 0) g_bR[w] = s;
}

// ---------------- layer 1 fused logits+scatter (unnormalized) --------------
__global__ void edge_fused1(const int* __restrict__ ei, const int* __restrict__ et,
                            const int* __restrict__ i2) {
    int e = (blockIdx.x * blockDim.x + threadIdx.x) >> 5;
    int lane = threadIdx.x & 31;
    if (e >= E_TOT) return;
    int row, col;
    const float* C0;
    const float* C1 = nullptr;
    float cadd;
    int h = lane >> 3;
    if (e < E_DIRN) {
        row = ei[E_DIRN + e];
        col = ei[e];
        int t = et[e];
        C0 = g_rC + t * 512 + 256;
        cadd = g_aC[t * 4 + h];
    } else {
        int q = (e - E_DIRN) * 4;
        row = i2[q + 3]; col = i2[q + 0];
        int t0 = i2[q + 1], t1 = i2[q + 2];
        C0 = g_rC + t0 * 512 + 256;
        C1 = g_rC + t1 * 512 + 256;
        cadd = g_aC[t0 * 4 + h] + g_aC[t1 * 4 + h];
    }
    float l = g_aA[row * 4 + h] + g_aB[col * 4 + h] + cadd;
    l = (l > 0.f) ? l : 0.2f * l;
    float w = expf(l);
    if ((lane & 7) == 0) atomicAdd(&g_s1[row * 4 + h], w);

    int d = lane * 8;
    const float* Bp = g_ABE + (size_t)col * 768 + 256;
    float* Ap = g_agg1 + (size_t)row * 256;
    float4 v0 = *(const float4*)(Bp + d);
    float4 v1 = *(const float4*)(Bp + d + 4);
    float4 c0 = *(const float4*)(C0 + d);
    float4 c1 = *(const float4*)(C0 + d + 4);
    v0.x += c0.x; v0.y += c0.y; v0.z += c0.z; v0.w += c0.w;
    v1.x += c1.x; v1.y += c1.y; v1.z += c1.z; v1.w += c1.w;
    if (C1) {
        float4 e0 = *(const float4*)(C1 + d);
        float4 e1 = *(const float4*)(C1 + d + 4);
        v0.x += e0.x; v0.y += e0.y; v0.z += e0.z; v0.w += e0.w;
        v1.x += e1.x; v1.y += e1.y; v1.z += e1.z; v1.w += e1.w;
    }
    v0.x *= w; v0.y *= w; v0.z *= w; v0.w *= w;
    v1.x *= w; v1.y *= w; v1.z *= w; v1.w *= w;
    red_add_v4(Ap + d, v0);
    red_add_v4(Ap + d + 4, v1);
}

// x = elu((aggw + A[v]*s) / (s + 1e-16))
__global__ void finalize1() {
    size_t gid = (size_t)blockIdx.x * blockDim.x + threadIdx.x;
    if (gid >= (size_t)N_ENT * 256) return;
    int v = (int)(gid >> 8);
    int d = (int)(gid & 255);
    int h = d >> 6;
    float s = g_s1[v * 4 + h];
    float val = (g_agg1[gid] + g_ABE[(size_t)v * 768 + d] * s) / (s + 1e-16f);
    g_agg1[gid] = (val > 0.f) ? val : expm1f(val);
}

// ---------------- layer 2 fused logits+scatter ------------------------------
__global__ void edge_fused2(const int* __restrict__ ei, const int* __restrict__ et,
                            const int* __restrict__ i2) {
    int e = (blockIdx.x * blockDim.x + threadIdx.x) >> 5;
    int lane = threadIdx.x & 31;
    if (e >= E_TOT) return;
    int row, col;
    const float* C0;
    const float* C1 = nullptr;
    float cadd;
    if (e < E_DIRN) {
        row = ei[E_DIRN + e]; col = ei[e];
        int t = et[e];
        C0 = g_R3 + t * 256;
        cadd = g_bR[t];
    } else {
        int q = (e - E_DIRN) * 4;
        row = i2[q + 3]; col = i2[q + 0];
        int t0 = i2[q + 1], t1 = i2[q + 2];
        C0 = g_R3 + t0 * 256;
        C1 = g_R3 + t1 * 256;
        cadd = g_bR[t0] + g_bR[t1];
    }
    float l = g_bx1[row] + g_bx2[col] + cadd;
    l = (l > 0.f) ? l : 0.2f * l;
    float w = expf(l);
    if (lane == 0) atomicAdd(&g_s2[row], w);

    int d = lane * 8;
    const float* Xp = g_X12 + (size_t)col * 512 + 256;
    float* Ap = g_agg2 + (size_t)row * 256;
    float4 v0 = *(const float4*)(Xp + d);
    float4 v1 = *(const float4*)(Xp + d + 4);
    float4 c0 = *(const float4*)(C0 + d);
    float4 c1 = *(const float4*)(C0 + d + 4);
    v0.x += c0.x; v0.y += c0.y; v0.z += c0.z; v0.w += c0.w;
    v1.x += c1.x; v1.y += c1.y; v1.z += c1.z; v1.w += c1.w;
    if (C1) {
        float4 e0 = *(const float4*)(C1 + d);
        float4 e1 = *(const float4*)(C1 + d + 4);
        v0.x += e0.x; v0.y += e0.y; v0.z += e0.z; v0.w += e0.w;
        v1.x += e1.x; v1.y += e1.y; v1.z += e1.z; v1.w += e1.w;
    }
    v0.x *= w; v0.y *= w; v0.z *= w; v0.w *= w;
    v1.x *= w; v1.y *= w; v1.z *= w; v1.w *= w;
    red_add_v4(Ap + d, v0);
    red_add_v4(Ap + d + 4, v1);
}

// out = elu((aggw2 + X1[v]*s)/(s+eps)) + ENT[v]; accumulate column sum/sumsq
#define ROWS_PER_BLK 128
__global__ void finalize2_bn(float* __restrict__ out) {
    int ct = threadIdx.x;
    int r0 = blockIdx.x * ROWS_PER_BLK;
    int r1 = min(r0 + ROWS_PER_BLK, N_ENT);
    float sum = 0.f, sq = 0.f;
    for (int r = r0; r < r1; r++) {
        float s = g_s2[r];
        float val = (g_agg2[(size_t)r * 256 + ct] + g_X12[(size_t)r * 512 + ct] * s) / (s + 1e-16f);
        val = (val > 0.f) ? val : expm1f(val);
        val += g_ABE[(size_t)r * 768 + 512 + ct];
        out[(size_t)r * 256 + ct] = val;
        sum += val;
        sq += val * val;
    }
    atomicAdd(&g_csum[ct], sum);
    atomicAdd(&g_csq[ct], sq);
}

__global__ void bn_norm(float* __restrict__ out, const float* __restrict__ gamma,
                        const float* __restrict__ beta) {
    size_t gid = (size_t)blockIdx.x * blockDim.x + threadIdx.x;
    if (gid >= (size_t)N_ENT * 256) return;
    int d = (int)(gid & 255);
    float mu = g_csum[d] * (1.0f / N_ENT);
    float var = g_csq[d] * (1.0f / N_ENT) - mu * mu;
    float inv = rsqrtf(var + 1e-5f);
    out[gid] = (out[gid] - mu) * inv * gamma[d] + beta[d];
}

__global__ void copy_r(float* __restrict__ out) {
    int gid = blockIdx.x * blockDim.x + threadIdx.x;
    if (gid < N_REL * 256)
        out[(size_t)N_ENT * 256 + gid] = g_rC[(gid >> 8) * 512 + (gid & 255)];
}

// ---------------- host orchestration ---------------------------------------
static void tf32_gemm(const float* A, const float* B, float* C, int M, int N, int K,
                      int lda, int ldb, int ldc) {
    dim3 grid(N / 128, (M + 127) / 128);
    tf32_gemm_kernel<<<grid, 256>>>(M, N, K, lda, ldb, ldc, A, B, C);
}
static void sgemm_small(const float* A, const float* B, float* C, int M, int N, int K,
                        int lda, int ldb, int ldc) {
    dim3 grid(N / 128, (M + 15) / 16);
    sgemm_small_kernel<<<grid, 256>>>(M, N, K, lda, ldb, ldc, A, B, C);
}

extern "C" void kernel_launch(void* const* d_in, const int* in_sizes, int n_in,
                              void* d_out, int out_size) {
    const int*   edge_index = (const int*)d_in[0];
    const int*   edge_type  = (const int*)d_in[1];
    const int*   ind2       = (const int*)d_in[2];
    const float* init_embed = (const float*)d_in[3];
    const float* init_rel   = (const float*)d_in[4];
    const float* W_heads    = (const float*)d_in[5];
    const float* a_heads    = (const float*)d_in[6];
    const float* gat_W      = (const float*)d_in[7];
    const float* out_W      = (const float*)d_in[8];
    const float* out_a      = (const float*)d_in[9];
    const float* W_entities = (const float*)d_in[10];
    const float* bn_gamma   = (const float*)d_in[11];
    const float* bn_beta    = (const float*)d_in[12];
    float* out = (float*)d_out;

    float *pABE, *prC, *pAgg1, *pX12, *pR3, *pW1E, *pWrC, *pW2ab;
    cudaGetSymbolAddress((void**)&pABE, g_ABE);
    cudaGetSymbolAddress((void**)&prC, g_rC);
    cudaGetSymbolAddress((void**)&pAgg1, g_agg1);
    cudaGetSymbolAddress((void**)&pX12, g_X12);
    cudaGetSymbolAddress((void**)&pR3, g_R3);
    cudaGetSymbolAddress((void**)&pW1E, g_W1E);
    cudaGetSymbolAddress((void**)&pWrC, g_WrC);
    cudaGetSymbolAddress((void**)&pW2ab, g_W2ab);

    zero_kernel<<<2048, 256>>>();
    pack_w1E<<<384, 256>>>(W_heads, W_entities);
    pack_w2<<<512, 256>>>(out_W);
    pack_wrC<<<256, 256>>>(gat_W, W_heads);
    sgemm_small(init_rel, pWrC, prC, N_REL, 512, 128, 128, 512, 512);        // [r|Crel]
    tf32_gemm(init_embed, pW1E, pABE, N_ENT, 768, 128, 128, 768, 768);       // [A|B|ENT]

    dots_ab<<<5000, 256>>>(a_heads);
    dots_c<<<8, 256>>>(a_heads);

    // layer 1 (fused logits + unnormalized scatter)
    edge_fused1<<<E_TOT / 8, 256>>>(edge_index, edge_type, ind2);
    finalize1<<<(N_ENT * 256 + 255) / 256, 256>>>();

    // layer 2 precompute
    tf32_gemm(pAgg1, pW2ab, pX12, N_ENT, 512, 256, 256, 512, 512);           // [X1|X2]
    sgemm_small(prC, out_W + 512 * 256, pR3, N_REL, 256, 256, 512, 256, 256);// R3
    dots_x<<<10000, 256>>>(out_a);
    dots_r<<<(N_REL * 32 + 255) / 256, 256>>>(out_a);

    // layer 2
    edge_fused2<<<E_TOT / 8, 256>>>(edge_index, edge_type, ind2);

    // epilogue: elu + residual + batchnorm, and r output
    finalize2_bn<<<(N_ENT + ROWS_PER_BLK - 1) / ROWS_PER_BLK, 256>>>(out);
    bn_norm<<<(N_ENT * 256 + 255) / 256, 256>>>(out, bn_gamma, bn_beta);
    copy_r<<<(N_REL * 256 + 255) / 256, 256>>>(out);
}